// round 14
// baseline (speedup 1.0000x reference)
#include <cuda_runtime.h>
#include <cuda_bf16.h>
#include <cstdint>
#include <cstddef>

#define N_NODES 100000
#define N_EDGES 1280000
#define D 64
#define SCAN_BLK 256
#define N_SCAN_BLKS ((N_NODES + SCAN_BLK - 1) / SCAN_BLK)   // 391

typedef unsigned long long u64;
typedef unsigned int u32;

#define FMA2(acc, a, b) \
    asm("fma.rn.f32x2 %0, %1, %2, %0;" : "+l"(acc) : "l"(a), "l"(b))
union F2U { u64 u; float2 f; };

// ---------------- scratch (static __device__, no allocations) ----------------
__device__ float4 g_S[(size_t)N_NODES * 32];   // [node][fwd64|rev64]
__device__ int g_deg[N_NODES];                  // histogram (kept zeroed)
__device__ int g_off[N_NODES + 1];
__device__ int g_cur[N_NODES];
__device__ int g_eid[N_EDGES];
__device__ int g_blksum[N_SCAN_BLKS];
__device__ int g_blkoff[N_SCAN_BLKS];

// ---------------------------- CSR build kernels -----------------------------
__global__ void k_hist(const int* __restrict__ dst) {
    int e = blockIdx.x * blockDim.x + threadIdx.x;
    if (e < N_EDGES) atomicAdd(&g_deg[dst[e]], 1);
}

__global__ __launch_bounds__(SCAN_BLK) void k_scanA() {
    __shared__ int sh[SCAN_BLK];
    int t = threadIdx.x;
    int i = blockIdx.x * SCAN_BLK + t;
    sh[t] = (i < N_NODES) ? g_deg[i] : 0;
    __syncthreads();
    #pragma unroll
    for (int d = SCAN_BLK / 2; d > 0; d >>= 1) {
        if (t < d) sh[t] += sh[t + d];
        __syncthreads();
    }
    if (t == 0) g_blksum[blockIdx.x] = sh[0];
}

__global__ __launch_bounds__(512) void k_scanB() {
    __shared__ int sh[512];
    int t = threadIdx.x;
    int v = (t < N_SCAN_BLKS) ? g_blksum[t] : 0;
    sh[t] = v;
    __syncthreads();
    for (int d = 1; d < 512; d <<= 1) {
        int x = (t >= d) ? sh[t - d] : 0;
        __syncthreads();
        sh[t] += x;
        __syncthreads();
    }
    if (t < N_SCAN_BLKS) g_blkoff[t] = sh[t] - v;
    if (t == 511) g_off[N_NODES] = sh[511];
}

__global__ __launch_bounds__(SCAN_BLK) void k_scanC() {
    __shared__ int sh[SCAN_BLK];
    int t = threadIdx.x;
    int i = blockIdx.x * SCAN_BLK + t;
    int v = (i < N_NODES) ? g_deg[i] : 0;
    sh[t] = v;
    __syncthreads();
    for (int d = 1; d < SCAN_BLK; d <<= 1) {
        int x = (t >= d) ? sh[t - d] : 0;
        __syncthreads();
        sh[t] += x;
        __syncthreads();
    }
    if (i < N_NODES) {
        int excl = sh[t] - v + g_blkoff[blockIdx.x];
        g_off[i] = excl;
        g_cur[i] = excl;
        g_deg[i] = 0;              // reset for next call (zero-init covers call 1)
    }
}

__global__ void k_perm(const int* __restrict__ dst) {
    int e = blockIdx.x * blockDim.x + threadIdx.x;
    if (e < N_EDGES) {
        int pos = atomicAdd(&g_cur[dst[e]], 1);
        g_eid[pos] = e;
    }
}

// ------------------------- gather-reduce aggregation -------------------------
__global__ __launch_bounds__(256) void k_agg(
    const float* __restrict__ node_feat,
    const float* __restrict__ edge_feat,
    const float* __restrict__ edge_norm,
    const int*   __restrict__ src,
    const int*   __restrict__ is_rev)
{
    int warp = (blockIdx.x * blockDim.x + threadIdx.x) >> 5;
    int l = threadIdx.x & 31;
    if (warp >= N_NODES) return;
    int n = warp;

    int beg = g_off[n];
    int end = g_off[n + 1];

    float2 f = make_float2(0.f, 0.f);
    float2 r = make_float2(0.f, 0.f);

    for (int p0 = beg; p0 < end; p0 += 32) {
        int m = end - p0; if (m > 32) m = 32;
        int e = 0, s = 0, rv = 0; float nr = 0.f;
        if (l < m) {
            e  = __ldg(&g_eid[p0 + l]);
            s  = __ldg(&src[e]);
            nr = __ldg(&edge_norm[e]);
            rv = __ldg(&is_rev[e]);
        }
        for (int j = 0; j < m; j++) {
            int   ee = __shfl_sync(0xffffffffu, e,  j);
            int   ss = __shfl_sync(0xffffffffu, s,  j);
            float nn = __shfl_sync(0xffffffffu, nr, j);
            int   rr = __shfl_sync(0xffffffffu, rv, j);
            float2 a = *reinterpret_cast<const float2*>(node_feat + (size_t)ss * 64 + 2 * l);
            float2 b = *reinterpret_cast<const float2*>(edge_feat + (size_t)ee * 64 + 2 * l);
            float mx = a.x * b.x * nn;
            float my = a.y * b.y * nn;
            if (rr) { r.x += mx; r.y += my; }
            else    { f.x += mx; f.y += my; }
        }
    }

    float* o = reinterpret_cast<float*>(g_S) + (size_t)n * 128;
    *reinterpret_cast<float2*>(o + 2 * l)      = f;
    *reinterpret_cast<float2*>(o + 64 + 2 * l) = r;
}

// ------------- split-bf16 mma.sync edge GEMM: out = edge_feat @ W -------------
// fp32 = hi(bf16, truncated) + lo(bf16 of residual); acc = hi*hi + hi*lo + lo*hi
// in f32 fragments (~16-17 mantissa bits => rel_err ~1e-5).
// Block: 128 thr / 64-edge x 64-col tile. Warp w owns rows [16w, 16w+16).
// SMEM rows padded to 144B (72 bf16) => conflict-free frag LDS.32.

#define SH_AH 0
#define SH_AL 9216
#define SH_BH 18432
#define SH_BL 27648
// total 36864 bytes static shared

#define MMA_BF16(c, a0, a1, a2, a3, b0, b1) \
    asm volatile( \
        "mma.sync.aligned.m16n8k16.row.col.f32.bf16.bf16.f32 " \
        "{%0,%1,%2,%3}, {%4,%5,%6,%7}, {%8,%9}, {%0,%1,%2,%3};" \
        : "+f"((c)[0]), "+f"((c)[1]), "+f"((c)[2]), "+f"((c)[3]) \
        : "r"(a0), "r"(a1), "r"(a2), "r"(a3), "r"(b0), "r"(b1))

__device__ __forceinline__ void cvt_hilo_pair(float f0, float f1,
                                              u32& hi, u32& lo) {
    u32 u0 = __float_as_uint(f0), u1 = __float_as_uint(f1);
    hi = __byte_perm(u0, u1, 0x7632);             // {bf16_trunc(f1):bf16_trunc(f0)}
    float l0 = f0 - __uint_as_float(u0 & 0xFFFF0000u);
    float l1 = f1 - __uint_as_float(u1 & 0xFFFF0000u);
    asm("cvt.rn.bf16x2.f32 %0, %1, %2;" : "=r"(lo) : "f"(l1), "f"(l0));
}

__global__ __launch_bounds__(128) void k_edge_mma(
    const float* __restrict__ edge_feat,
    const float* __restrict__ rel_w,
    float* __restrict__ edge_out)
{
    __shared__ char sm[36864];

    const int tid = threadIdx.x;
    const int e0  = blockIdx.x * 64;

    // --- A: edge_feat tile [64 rows x 64 k] -> hi/lo bf16 smem ---
    {
        const float4* Ag = reinterpret_cast<const float4*>(edge_feat) + (size_t)e0 * 16;
        #pragma unroll
        for (int it = 0; it < 8; it++) {
            int idx = it * 128 + tid;        // 0..1023
            int r  = idx >> 4;
            int q  = idx & 15;               // float4 index; k0 = 4q
            float4 v = Ag[(size_t)r * 16 + q];
            u32 h0, l0, h1, l1;
            cvt_hilo_pair(v.x, v.y, h0, l0);
            cvt_hilo_pair(v.z, v.w, h1, l1);
            int byte = r * 144 + q * 8;
            *reinterpret_cast<uint2*>(sm + SH_AH + byte) = make_uint2(h0, h1);
            *reinterpret_cast<uint2*>(sm + SH_AL + byte) = make_uint2(l0, l1);
        }
    }

    // --- B: rel_w [k][n] -> transposed bf16 hi/lo smem Wt[n][k] ---
    {
        const float4* Wg = reinterpret_cast<const float4*>(rel_w);
        #pragma unroll
        for (int it = 0; it < 8; it++) {
            int idx = it * 128 + tid;        // 0..1023
            int k  = idx >> 4;
            int n0 = (idx & 15) * 4;
            float4 v = Wg[idx];
            #pragma unroll
            for (int j = 0; j < 4; j++) {
                float f = (j == 0) ? v.x : (j == 1) ? v.y : (j == 2) ? v.z : v.w;
                u32 u = __float_as_uint(f);
                int off = (n0 + j) * 144 + k * 2;
                *reinterpret_cast<uint16_t*>(sm + SH_BH + off) = (uint16_t)(u >> 16);
                float l = f - __uint_as_float(u & 0xFFFF0000u);
                *reinterpret_cast<__nv_bfloat16*>(sm + SH_BL + off) = __float2bfloat16(l);
            }
        }
    }
    __syncthreads();

    // --- mma mainloop ---
    const int w    = tid >> 5;
    const int lane = tid & 31;
    const int gid  = lane >> 2;          // 0..7
    const int t2   = (lane & 3) * 2;     // k-pair / col-pair base
    const int ra   = w * 16 + gid;       // fragment rows ra, ra+8

    float c[8][4];
    #pragma unroll
    for (int j = 0; j < 8; j++)
        #pragma unroll
        for (int q = 0; q < 4; q++) c[j][q] = 0.f;

    #pragma unroll
    for (int ks = 0; ks < 4; ks++) {
        int aoff = (ks * 16 + t2) * 2;   // byte offset of k-pair within row
        u32 ah0 = *reinterpret_cast<u32*>(sm + SH_AH + ra * 144 + aoff);
        u32 ah1 = *reinterpret_cast<u32*>(sm + SH_AH + (ra + 8) * 144 + aoff);
        u32 ah2 = *reinterpret_cast<u32*>(sm + SH_AH + ra * 144 + aoff + 16);
        u32 ah3 = *reinterpret_cast<u32*>(sm + SH_AH + (ra + 8) * 144 + aoff + 16);
        u32 al0 = *reinterpret_cast<u32*>(sm + SH_AL + ra * 144 + aoff);
        u32 al1 = *reinterpret_cast<u32*>(sm + SH_AL + (ra + 8) * 144 + aoff);
        u32 al2 = *reinterpret_cast<u32*>(sm + SH_AL + ra * 144 + aoff + 16);
        u32 al3 = *reinterpret_cast<u32*>(sm + SH_AL + (ra + 8) * 144 + aoff + 16);
        #pragma unroll
        for (int j = 0; j < 8; j++) {
            int coff = (j * 8 + gid) * 144 + aoff;
            u32 bh0 = *reinterpret_cast<u32*>(sm + SH_BH + coff);
            u32 bh1 = *reinterpret_cast<u32*>(sm + SH_BH + coff + 16);
            u32 bl0 = *reinterpret_cast<u32*>(sm + SH_BL + coff);
            u32 bl1 = *reinterpret_cast<u32*>(sm + SH_BL + coff + 16);
            MMA_BF16(c[j], ah0, ah1, ah2, ah3, bh0, bh1);
            MMA_BF16(c[j], ah0, ah1, ah2, ah3, bl0, bl1);
            MMA_BF16(c[j], al0, al1, al2, al3, bh0, bh1);
        }
    }

    // --- epilogue: fragment rows ra / ra+8, cols j*8 + t2 (+1) ---
    {
        float* oa = edge_out + (size_t)(e0 + ra) * 64;
        float* ob = edge_out + (size_t)(e0 + ra + 8) * 64;
        #pragma unroll
        for (int j = 0; j < 8; j++) {
            *reinterpret_cast<float2*>(oa + j * 8 + t2) = make_float2(c[j][0], c[j][1]);
            *reinterpret_cast<float2*>(ob + j * 8 + t2) = make_float2(c[j][2], c[j][3]);
        }
    }
}

// ----------------------------- node GEMM kernel ------------------------------
__global__ __launch_bounds__(64) void k_node(
    const float* __restrict__ node_feat,
    const float* __restrict__ in_w,
    const float* __restrict__ out_w,
    const float* __restrict__ loop_w,
    const float* __restrict__ loop_rel,
    const float* __restrict__ bias,
    float* __restrict__ node_out)
{
    __shared__ float Xs[64][68];
    __shared__ float Wt[64][68];

    const int t  = threadIdx.x;
    const int r0 = blockIdx.x * 64;
    const int tx = t & 7;
    const int ty = t >> 3;
    const float* S = reinterpret_cast<const float*>(g_S);

    u64 acc[8][8];
    #pragma unroll
    for (int i = 0; i < 8; i++)
        #pragma unroll
        for (int j = 0; j < 8; j++) acc[i][j] = 0ull;

    #pragma unroll 1
    for (int ch = 0; ch < 3; ch++) {
        if (ch == 2) {
            #pragma unroll 8
            for (int k = 0; k < 64; k++)
                Wt[t][k] = loop_w[k * 64 + t] * loop_rel[k];
        } else {
            const float* W = (ch == 0) ? in_w : out_w;
            #pragma unroll 8
            for (int k = 0; k < 64; k++)
                Wt[t][k] = W[k * 64 + t];
        }

        const float* Xbase;
        size_t pitch, off;
        if (ch == 0)      { Xbase = S;         pitch = 128; off = 0;  }
        else if (ch == 1) { Xbase = S;         pitch = 128; off = 64; }
        else              { Xbase = node_feat; pitch = 64;  off = 0;  }

        #pragma unroll
        for (int it = 0; it < 16; it++) {
            int idx = it * 64 + t;
            int rr = idx >> 4;
            int kq = idx & 15;
            int gr = r0 + rr;
            float4 v = make_float4(0.f, 0.f, 0.f, 0.f);
            if (gr < N_NODES)
                v = *reinterpret_cast<const float4*>(Xbase + (size_t)gr * pitch + off + kq * 4);
            *reinterpret_cast<float4*>(&Xs[rr][kq * 4]) = v;
        }
        __syncthreads();

        #pragma unroll 4
        for (int k4 = 0; k4 < 16; k4++) {
            ulonglong2 xv[8], wv[8];
            #pragma unroll
            for (int i = 0; i < 8; i++)
                xv[i] = *reinterpret_cast<const ulonglong2*>(&Xs[ty + 8 * i][k4 * 4]);
            #pragma unroll
            for (int j = 0; j < 8; j++)
                wv[j] = *reinterpret_cast<const ulonglong2*>(&Wt[tx + 8 * j][k4 * 4]);
            #pragma unroll
            for (int i = 0; i < 8; i++)
                #pragma unroll
                for (int j = 0; j < 8; j++)
                    FMA2(acc[i][j], xv[i].x, wv[j].x);
            #pragma unroll
            for (int i = 0; i < 8; i++)
                #pragma unroll
                for (int j = 0; j < 8; j++)
                    FMA2(acc[i][j], xv[i].y, wv[j].y);
        }
        __syncthreads();
    }

    #pragma unroll
    for (int i = 0; i < 8; i++) {
        int rr = r0 + ty + 8 * i;
        if (rr < N_NODES) {
            float* o = node_out + (size_t)rr * 64;
            #pragma unroll
            for (int j = 0; j < 8; j++) {
                int c = tx + 8 * j;
                F2U cv; cv.u = acc[i][j];
                o[c] = (cv.f.x + cv.f.y) * 0.3333333f + __ldg(&bias[c]);
            }
        }
    }
}

// ---------------------------------------------------------------------------
// kernel_launch — inputs in setup_inputs dict order; is_rev is int32.
// Output: node_out [N,64] then edge_out [E,64], f32. Single stream (stream
// fork/join measured neutral in R13). Launch order puts k_edge_mma at
// sampled index 3 for ncu.
// ---------------------------------------------------------------------------
extern "C" void kernel_launch(void* const* d_in, const int* in_sizes, int n_in,
                              void* d_out, int out_size)
{
    const float* node_feat = (const float*)d_in[0];
    const float* edge_feat = (const float*)d_in[1];
    const float* edge_norm = (const float*)d_in[2];
    const int*   src       = (const int*)d_in[3];
    const int*   dst       = (const int*)d_in[4];
    const int*   is_rev    = (const int*)d_in[5];
    const float* in_w      = (const float*)d_in[6];
    const float* out_w     = (const float*)d_in[7];
    const float* rel_w     = (const float*)d_in[8];
    const float* loop_w    = (const float*)d_in[9];
    const float* loop_rel  = (const float*)d_in[10];
    const float* bias      = (const float*)d_in[11];

    float* out      = (float*)d_out;
    float* node_out = out;

    int write_edge = (out_size >= (N_NODES + N_EDGES) * D) ? 1 : 0;
    float* edge_out = write_edge ? (out + (size_t)N_NODES * D) : nullptr;

    k_hist<<<(N_EDGES + 255) / 256, 256>>>(dst);                 // 0
    k_scanA<<<N_SCAN_BLKS, SCAN_BLK>>>();                        // 1
    k_scanB<<<1, 512>>>();                                       // 2
    if (write_edge)
        k_edge_mma<<<N_EDGES / 64, 128>>>(edge_feat, rel_w, edge_out);  // 3
    k_scanC<<<N_SCAN_BLKS, SCAN_BLK>>>();                        // 4
    k_perm<<<(N_EDGES + 255) / 256, 256>>>(dst);                 // 5
    k_agg<<<(N_NODES * 32 + 255) / 256, 256>>>(node_feat, edge_feat,
                                               edge_norm, src, is_rev); // 6
    k_node<<<(N_NODES + 63) / 64, 64>>>(node_feat, in_w, out_w,
                                        loop_w, loop_rel, bias, node_out); // 7
}

// round 16
// speedup vs baseline: 1.0031x; 1.0031x over previous
#include <cuda_runtime.h>
#include <cuda_bf16.h>
#include <cstdint>
#include <cstddef>

#define N_NODES 100000
#define N_EDGES 1280000
#define D 64
#define SCAN_BLK 256
#define N_SCAN_BLKS ((N_NODES + SCAN_BLK - 1) / SCAN_BLK)   // 391

typedef unsigned long long u64;
typedef unsigned int u32;

#define FMA2(acc, a, b) \
    asm("fma.rn.f32x2 %0, %1, %2, %0;" : "+l"(acc) : "l"(a), "l"(b))
union F2U { u64 u; float2 f; };

// ---------------- scratch (static __device__, no allocations) ----------------
__device__ float4 g_S[(size_t)N_NODES * 32];   // [node][fwd64|rev64]
__device__ int g_deg[N_NODES];                  // histogram (kept zeroed)
__device__ int g_off[N_NODES + 1];
__device__ int g_cur[N_NODES];
__device__ int g_eid[N_EDGES];
__device__ int g_blksum[N_SCAN_BLKS];
__device__ int g_blkoff[N_SCAN_BLKS];

// ---------------------------- CSR build kernels -----------------------------
__global__ void k_hist(const int* __restrict__ dst) {
    int e = blockIdx.x * blockDim.x + threadIdx.x;
    if (e < N_EDGES) atomicAdd(&g_deg[dst[e]], 1);
}

__global__ __launch_bounds__(SCAN_BLK) void k_scanA() {
    __shared__ int sh[SCAN_BLK];
    int t = threadIdx.x;
    int i = blockIdx.x * SCAN_BLK + t;
    sh[t] = (i < N_NODES) ? g_deg[i] : 0;
    __syncthreads();
    #pragma unroll
    for (int d = SCAN_BLK / 2; d > 0; d >>= 1) {
        if (t < d) sh[t] += sh[t + d];
        __syncthreads();
    }
    if (t == 0) g_blksum[blockIdx.x] = sh[0];
}

__global__ __launch_bounds__(512) void k_scanB() {
    __shared__ int sh[512];
    int t = threadIdx.x;
    int v = (t < N_SCAN_BLKS) ? g_blksum[t] : 0;
    sh[t] = v;
    __syncthreads();
    for (int d = 1; d < 512; d <<= 1) {
        int x = (t >= d) ? sh[t - d] : 0;
        __syncthreads();
        sh[t] += x;
        __syncthreads();
    }
    if (t < N_SCAN_BLKS) g_blkoff[t] = sh[t] - v;
    if (t == 511) g_off[N_NODES] = sh[511];
}

__global__ __launch_bounds__(SCAN_BLK) void k_scanC() {
    __shared__ int sh[SCAN_BLK];
    int t = threadIdx.x;
    int i = blockIdx.x * SCAN_BLK + t;
    int v = (i < N_NODES) ? g_deg[i] : 0;
    sh[t] = v;
    __syncthreads();
    for (int d = 1; d < SCAN_BLK; d <<= 1) {
        int x = (t >= d) ? sh[t - d] : 0;
        __syncthreads();
        sh[t] += x;
        __syncthreads();
    }
    if (i < N_NODES) {
        int excl = sh[t] - v + g_blkoff[blockIdx.x];
        g_off[i] = excl;
        g_cur[i] = excl;
        g_deg[i] = 0;              // reset for next call (zero-init covers call 1)
    }
}

__global__ void k_perm(const int* __restrict__ dst) {
    int e = blockIdx.x * blockDim.x + threadIdx.x;
    if (e < N_EDGES) {
        int pos = atomicAdd(&g_cur[dst[e]], 1);
        g_eid[pos] = e;
    }
}

// ------------------------- gather-reduce aggregation -------------------------
__global__ __launch_bounds__(256) void k_agg(
    const float* __restrict__ node_feat,
    const float* __restrict__ edge_feat,
    const float* __restrict__ edge_norm,
    const int*   __restrict__ src,
    const int*   __restrict__ is_rev)
{
    int warp = (blockIdx.x * blockDim.x + threadIdx.x) >> 5;
    int l = threadIdx.x & 31;
    if (warp >= N_NODES) return;
    int n = warp;

    int beg = g_off[n];
    int end = g_off[n + 1];

    float2 f = make_float2(0.f, 0.f);
    float2 r = make_float2(0.f, 0.f);

    for (int p0 = beg; p0 < end; p0 += 32) {
        int m = end - p0; if (m > 32) m = 32;
        int e = 0, s = 0, rv = 0; float nr = 0.f;
        if (l < m) {
            e  = __ldg(&g_eid[p0 + l]);
            s  = __ldg(&src[e]);
            nr = __ldg(&edge_norm[e]);
            rv = __ldg(&is_rev[e]);
        }
        for (int j = 0; j < m; j++) {
            int   ee = __shfl_sync(0xffffffffu, e,  j);
            int   ss = __shfl_sync(0xffffffffu, s,  j);
            float nn = __shfl_sync(0xffffffffu, nr, j);
            int   rr = __shfl_sync(0xffffffffu, rv, j);
            float2 a = *reinterpret_cast<const float2*>(node_feat + (size_t)ss * 64 + 2 * l);
            float2 b = *reinterpret_cast<const float2*>(edge_feat + (size_t)ee * 64 + 2 * l);
            float mx = a.x * b.x * nn;
            float my = a.y * b.y * nn;
            if (rr) { r.x += mx; r.y += my; }
            else    { f.x += mx; f.y += my; }
        }
    }

    float* o = reinterpret_cast<float*>(g_S) + (size_t)n * 128;
    *reinterpret_cast<float2*>(o + 2 * l)      = f;
    *reinterpret_cast<float2*>(o + 64 + 2 * l) = r;
}

// ------------- split-bf16 mma.sync edge GEMM: out = edge_feat @ W -------------
// fp32 = hi(bf16, truncated) + lo(bf16 of residual); acc = hi*hi + hi*lo + lo*hi
// in f32 fragments (~16-17 mantissa bits => rel_err ~1e-5).
// Fragments fed via ldmatrix.x4 (10 per k-step vs 40 LDS.32 in R14 — the L1
// port was 96.4% busy and is the measured bottleneck).
// SMEM rows padded to 144B: rows r hit bank groups 4r mod 32 => ldmatrix
// conflict-free.

#define SH_AH 0
#define SH_AL 9216
#define SH_BH 18432
#define SH_BL 27648
// total 36864 bytes static shared

#define MMA_BF16(c, a0, a1, a2, a3, b0, b1) \
    asm volatile( \
        "mma.sync.aligned.m16n8k16.row.col.f32.bf16.bf16.f32 " \
        "{%0,%1,%2,%3}, {%4,%5,%6,%7}, {%8,%9}, {%0,%1,%2,%3};" \
        : "+f"((c)[0]), "+f"((c)[1]), "+f"((c)[2]), "+f"((c)[3]) \
        : "r"(a0), "r"(a1), "r"(a2), "r"(a3), "r"(b0), "r"(b1))

#define LDSM4(r, addr) \
    asm volatile( \
        "ldmatrix.sync.aligned.m8n8.x4.shared.b16 {%0,%1,%2,%3}, [%4];" \
        : "=r"((r)[0]), "=r"((r)[1]), "=r"((r)[2]), "=r"((r)[3]) \
        : "r"(addr))

__device__ __forceinline__ void cvt_hilo_pair(float f0, float f1,
                                              u32& hi, u32& lo) {
    u32 u0 = __float_as_uint(f0), u1 = __float_as_uint(f1);
    hi = __byte_perm(u0, u1, 0x7632);             // {bf16_trunc(f1):bf16_trunc(f0)}
    float l0 = f0 - __uint_as_float(u0 & 0xFFFF0000u);
    float l1 = f1 - __uint_as_float(u1 & 0xFFFF0000u);
    asm("cvt.rn.bf16x2.f32 %0, %1, %2;" : "=r"(lo) : "f"(l1), "f"(l0));
}

__global__ __launch_bounds__(128) void k_edge_mma(
    const float* __restrict__ edge_feat,
    const float* __restrict__ rel_w,
    float* __restrict__ edge_out)
{
    __shared__ char sm[36864];

    const int tid = threadIdx.x;
    const int e0  = blockIdx.x * 64;

    // --- A: edge_feat tile [64 rows x 64 k] -> hi/lo bf16 smem ---
    {
        const float4* Ag = reinterpret_cast<const float4*>(edge_feat) + (size_t)e0 * 16;
        #pragma unroll
        for (int it = 0; it < 8; it++) {
            int idx = it * 128 + tid;        // 0..1023
            int r  = idx >> 4;
            int q  = idx & 15;               // float4 index; k0 = 4q
            float4 v = Ag[(size_t)r * 16 + q];
            u32 h0, l0, h1, l1;
            cvt_hilo_pair(v.x, v.y, h0, l0);
            cvt_hilo_pair(v.z, v.w, h1, l1);
            int byte = r * 144 + q * 8;
            *reinterpret_cast<uint2*>(sm + SH_AH + byte) = make_uint2(h0, h1);
            *reinterpret_cast<uint2*>(sm + SH_AL + byte) = make_uint2(l0, l1);
        }
    }

    // --- B: rel_w [k][n] -> transposed bf16 hi/lo smem Wt[n][k] ---
    {
        const float4* Wg = reinterpret_cast<const float4*>(rel_w);
        #pragma unroll
        for (int it = 0; it < 8; it++) {
            int idx = it * 128 + tid;        // 0..1023
            int k  = idx >> 4;
            int n0 = (idx & 15) * 4;
            float4 v = Wg[idx];
            #pragma unroll
            for (int j = 0; j < 4; j++) {
                float f = (j == 0) ? v.x : (j == 1) ? v.y : (j == 2) ? v.z : v.w;
                u32 u = __float_as_uint(f);
                int off = (n0 + j) * 144 + k * 2;
                *reinterpret_cast<uint16_t*>(sm + SH_BH + off) = (uint16_t)(u >> 16);
                float l = f - __uint_as_float(u & 0xFFFF0000u);
                *reinterpret_cast<__nv_bfloat16*>(sm + SH_BL + off) = __float2bfloat16(l);
            }
        }
    }
    __syncthreads();

    // --- mma mainloop (ldmatrix-fed) ---
    const int w    = tid >> 5;
    const int lane = tid & 31;
    const int gid  = lane >> 2;          // 0..7
    const int t2   = (lane & 3) * 2;     // col-pair base
    const int ra   = w * 16 + gid;       // fragment rows ra, ra+8

    u32 smb = (u32)__cvta_generic_to_shared(sm);

    // A ldmatrix lane address: tiles {rows 0-7, rows 8-15} x {k 0-7, k 8-15}
    int arow = w * 16 + ((lane >> 3) & 1) * 8 + (lane & 7);
    u32 aoff = (u32)(arow * 144 + (lane >> 4) * 16);
    u32 ah_a = smb + SH_AH + aoff;
    u32 al_a = smb + SH_AL + aoff;

    // B ldmatrix lane addresses per j-pair p: tiles {j=2p, j=2p+1} x {k-half}
    int bn = lane & 7;
    int kh = (lane >> 3) & 1;
    int js = lane >> 4;                  // 0,1 selects j within pair
    u32 bh_a[4], bl_a[4];
    #pragma unroll
    for (int p = 0; p < 4; p++) {
        u32 boff = (u32)(((2 * p + js) * 8 + bn) * 144 + kh * 16);
        bh_a[p] = smb + SH_BH + boff;
        bl_a[p] = smb + SH_BL + boff;
    }

    float c[8][4];
    #pragma unroll
    for (int j = 0; j < 8; j++)
        #pragma unroll
        for (int q = 0; q < 4; q++) c[j][q] = 0.f;

    #pragma unroll
    for (int ks = 0; ks < 4; ks++) {
        u32 ko = ks * 32;                // k-step byte offset (16 bf16)
        u32 ah[4], al[4];
        LDSM4(ah, ah_a + ko);
        LDSM4(al, al_a + ko);
        #pragma unroll
        for (int p = 0; p < 4; p++) {
            u32 bh[4], bl[4];
            LDSM4(bh, bh_a[p] + ko);
            LDSM4(bl, bl_a[p] + ko);
            MMA_BF16(c[2 * p],     ah[0], ah[1], ah[2], ah[3], bh[0], bh[1]);
            MMA_BF16(c[2 * p],     ah[0], ah[1], ah[2], ah[3], bl[0], bl[1]);
            MMA_BF16(c[2 * p],     al[0], al[1], al[2], al[3], bh[0], bh[1]);
            MMA_BF16(c[2 * p + 1], ah[0], ah[1], ah[2], ah[3], bh[2], bh[3]);
            MMA_BF16(c[2 * p + 1], ah[0], ah[1], ah[2], ah[3], bl[2], bl[3]);
            MMA_BF16(c[2 * p + 1], al[0], al[1], al[2], al[3], bh[2], bh[3]);
        }
    }

    // --- epilogue: fragment rows ra / ra+8, cols j*8 + t2 (+1) ---
    {
        float* oa = edge_out + (size_t)(e0 + ra) * 64;
        float* ob = edge_out + (size_t)(e0 + ra + 8) * 64;
        #pragma unroll
        for (int j = 0; j < 8; j++) {
            *reinterpret_cast<float2*>(oa + j * 8 + t2) = make_float2(c[j][0], c[j][1]);
            *reinterpret_cast<float2*>(ob + j * 8 + t2) = make_float2(c[j][2], c[j][3]);
        }
    }
}

// ----------------------------- node GEMM kernel ------------------------------
__global__ __launch_bounds__(64) void k_node(
    const float* __restrict__ node_feat,
    const float* __restrict__ in_w,
    const float* __restrict__ out_w,
    const float* __restrict__ loop_w,
    const float* __restrict__ loop_rel,
    const float* __restrict__ bias,
    float* __restrict__ node_out)
{
    __shared__ float Xs[64][68];
    __shared__ float Wt[64][68];

    const int t  = threadIdx.x;
    const int r0 = blockIdx.x * 64;
    const int tx = t & 7;
    const int ty = t >> 3;
    const float* S = reinterpret_cast<const float*>(g_S);

    u64 acc[8][8];
    #pragma unroll
    for (int i = 0; i < 8; i++)
        #pragma unroll
        for (int j = 0; j < 8; j++) acc[i][j] = 0ull;

    #pragma unroll 1
    for (int ch = 0; ch < 3; ch++) {
        if (ch == 2) {
            #pragma unroll 8
            for (int k = 0; k < 64; k++)
                Wt[t][k] = loop_w[k * 64 + t] * loop_rel[k];
        } else {
            const float* W = (ch == 0) ? in_w : out_w;
            #pragma unroll 8
            for (int k = 0; k < 64; k++)
                Wt[t][k] = W[k * 64 + t];
        }

        const float* Xbase;
        size_t pitch, off;
        if (ch == 0)      { Xbase = S;         pitch = 128; off = 0;  }
        else if (ch == 1) { Xbase = S;         pitch = 128; off = 64; }
        else              { Xbase = node_feat; pitch = 64;  off = 0;  }

        #pragma unroll
        for (int it = 0; it < 16; it++) {
            int idx = it * 64 + t;
            int rr = idx >> 4;
            int kq = idx & 15;
            int gr = r0 + rr;
            float4 v = make_float4(0.f, 0.f, 0.f, 0.f);
            if (gr < N_NODES)
                v = *reinterpret_cast<const float4*>(Xbase + (size_t)gr * pitch + off + kq * 4);
            *reinterpret_cast<float4*>(&Xs[rr][kq * 4]) = v;
        }
        __syncthreads();

        #pragma unroll 4
        for (int k4 = 0; k4 < 16; k4++) {
            ulonglong2 xv[8], wv[8];
            #pragma unroll
            for (int i = 0; i < 8; i++)
                xv[i] = *reinterpret_cast<const ulonglong2*>(&Xs[ty + 8 * i][k4 * 4]);
            #pragma unroll
            for (int j = 0; j < 8; j++)
                wv[j] = *reinterpret_cast<const ulonglong2*>(&Wt[tx + 8 * j][k4 * 4]);
            #pragma unroll
            for (int i = 0; i < 8; i++)
                #pragma unroll
                for (int j = 0; j < 8; j++)
                    FMA2(acc[i][j], xv[i].x, wv[j].x);
            #pragma unroll
            for (int i = 0; i < 8; i++)
                #pragma unroll
                for (int j = 0; j < 8; j++)
                    FMA2(acc[i][j], xv[i].y, wv[j].y);
        }
        __syncthreads();
    }

    #pragma unroll
    for (int i = 0; i < 8; i++) {
        int rr = r0 + ty + 8 * i;
        if (rr < N_NODES) {
            float* o = node_out + (size_t)rr * 64;
            #pragma unroll
            for (int j = 0; j < 8; j++) {
                int c = tx + 8 * j;
                F2U cv; cv.u = acc[i][j];
                o[c] = (cv.f.x + cv.f.y) * 0.3333333f + __ldg(&bias[c]);
            }
        }
    }
}

// ---------------------------------------------------------------------------
// kernel_launch — inputs in setup_inputs dict order; is_rev is int32.
// Output: node_out [N,64] then edge_out [E,64], f32. Single stream.
// Launch order keeps k_edge_mma at sampled index 3 for ncu.
// ---------------------------------------------------------------------------
extern "C" void kernel_launch(void* const* d_in, const int* in_sizes, int n_in,
                              void* d_out, int out_size)
{
    const float* node_feat = (const float*)d_in[0];
    const float* edge_feat = (const float*)d_in[1];
    const float* edge_norm = (const float*)d_in[2];
    const int*   src       = (const int*)d_in[3];
    const int*   dst       = (const int*)d_in[4];
    const int*   is_rev    = (const int*)d_in[5];
    const float* in_w      = (const float*)d_in[6];
    const float* out_w     = (const float*)d_in[7];
    const float* rel_w     = (const float*)d_in[8];
    const float* loop_w    = (const float*)d_in[9];
    const float* loop_rel  = (const float*)d_in[10];
    const float* bias      = (const float*)d_in[11];

    float* out      = (float*)d_out;
    float* node_out = out;

    int write_edge = (out_size >= (N_NODES + N_EDGES) * D) ? 1 : 0;
    float* edge_out = write_edge ? (out + (size_t)N_NODES * D) : nullptr;

    k_hist<<<(N_EDGES + 255) / 256, 256>>>(dst);                 // 0
    k_scanA<<<N_SCAN_BLKS, SCAN_BLK>>>();                        // 1
    k_scanB<<<1, 512>>>();                                       // 2
    if (write_edge)
        k_edge_mma<<<N_EDGES / 64, 128>>>(edge_feat, rel_w, edge_out);  // 3
    k_scanC<<<N_SCAN_BLKS, SCAN_BLK>>>();                        // 4
    k_perm<<<(N_EDGES + 255) / 256, 256>>>(dst);                 // 5
    k_agg<<<(N_NODES * 32 + 255) / 256, 256>>>(node_feat, edge_feat,
                                               edge_norm, src, is_rev); // 6
    k_node<<<(N_NODES + 63) / 64, 64>>>(node_feat, in_w, out_w,
                                        loop_w, loop_rel, bias, node_out); // 7
}

// round 17
// speedup vs baseline: 1.3668x; 1.3626x over previous
#include <cuda_runtime.h>
#include <cuda_bf16.h>
#include <cstdint>
#include <cstddef>

#define N_NODES 100000
#define N_EDGES 1280000
#define D 64
#define SCAN_BLK 256
#define N_SCAN_BLKS ((N_NODES + SCAN_BLK - 1) / SCAN_BLK)   // 391

typedef unsigned long long u64;
typedef unsigned int u32;

#define FMA2(acc, a, b) \
    asm("fma.rn.f32x2 %0, %1, %2, %0;" : "+l"(acc) : "l"(a), "l"(b))
union F2U { u64 u; float2 f; };

// ---------------- scratch (static __device__, no allocations) ----------------
__device__ float4 g_S[(size_t)N_NODES * 32];   // [node][fwd64|rev64]
__device__ int g_deg[N_NODES];                  // histogram (kept zeroed)
__device__ int g_off[N_NODES + 1];
__device__ int g_cur[N_NODES];
__device__ int g_eid[N_EDGES];
__device__ int g_blksum[N_SCAN_BLKS];
__device__ int g_blkoff[N_SCAN_BLKS];
// Precomputed B fragments: slot = (ks*4+p)*2 + (0=hi,1=lo); [slot][lane] uint4
__device__ uint4 g_Bfrag[32][32];

// ---------------------------- CSR build kernels -----------------------------
__global__ void k_hist(const int* __restrict__ dst) {
    int e = blockIdx.x * blockDim.x + threadIdx.x;
    if (e < N_EDGES) atomicAdd(&g_deg[dst[e]], 1);
}

__global__ __launch_bounds__(SCAN_BLK) void k_scanA() {
    __shared__ int sh[SCAN_BLK];
    int t = threadIdx.x;
    int i = blockIdx.x * SCAN_BLK + t;
    sh[t] = (i < N_NODES) ? g_deg[i] : 0;
    __syncthreads();
    #pragma unroll
    for (int d = SCAN_BLK / 2; d > 0; d >>= 1) {
        if (t < d) sh[t] += sh[t + d];
        __syncthreads();
    }
    if (t == 0) g_blksum[blockIdx.x] = sh[0];
}

__global__ __launch_bounds__(512) void k_scanB() {
    __shared__ int sh[512];
    int t = threadIdx.x;
    int v = (t < N_SCAN_BLKS) ? g_blksum[t] : 0;
    sh[t] = v;
    __syncthreads();
    for (int d = 1; d < 512; d <<= 1) {
        int x = (t >= d) ? sh[t - d] : 0;
        __syncthreads();
        sh[t] += x;
        __syncthreads();
    }
    if (t < N_SCAN_BLKS) g_blkoff[t] = sh[t] - v;
    if (t == 511) g_off[N_NODES] = sh[511];
}

__global__ __launch_bounds__(SCAN_BLK) void k_scanC() {
    __shared__ int sh[SCAN_BLK];
    int t = threadIdx.x;
    int i = blockIdx.x * SCAN_BLK + t;
    int v = (i < N_NODES) ? g_deg[i] : 0;
    sh[t] = v;
    __syncthreads();
    for (int d = 1; d < SCAN_BLK; d <<= 1) {
        int x = (t >= d) ? sh[t - d] : 0;
        __syncthreads();
        sh[t] += x;
        __syncthreads();
    }
    if (i < N_NODES) {
        int excl = sh[t] - v + g_blkoff[blockIdx.x];
        g_off[i] = excl;
        g_cur[i] = excl;
        g_deg[i] = 0;              // reset for next call (zero-init covers call 1)
    }
}

__global__ void k_perm(const int* __restrict__ dst) {
    int e = blockIdx.x * blockDim.x + threadIdx.x;
    if (e < N_EDGES) {
        int pos = atomicAdd(&g_cur[dst[e]], 1);
        g_eid[pos] = e;
    }
}

// ------------------------- gather-reduce aggregation -------------------------
__global__ __launch_bounds__(256) void k_agg(
    const float* __restrict__ node_feat,
    const float* __restrict__ edge_feat,
    const float* __restrict__ edge_norm,
    const int*   __restrict__ src,
    const int*   __restrict__ is_rev)
{
    int warp = (blockIdx.x * blockDim.x + threadIdx.x) >> 5;
    int l = threadIdx.x & 31;
    if (warp >= N_NODES) return;
    int n = warp;

    int beg = g_off[n];
    int end = g_off[n + 1];

    float2 f = make_float2(0.f, 0.f);
    float2 r = make_float2(0.f, 0.f);

    for (int p0 = beg; p0 < end; p0 += 32) {
        int m = end - p0; if (m > 32) m = 32;
        int e = 0, s = 0, rv = 0; float nr = 0.f;
        if (l < m) {
            e  = __ldg(&g_eid[p0 + l]);
            s  = __ldg(&src[e]);
            nr = __ldg(&edge_norm[e]);
            rv = __ldg(&is_rev[e]);
        }
        for (int j = 0; j < m; j++) {
            int   ee = __shfl_sync(0xffffffffu, e,  j);
            int   ss = __shfl_sync(0xffffffffu, s,  j);
            float nn = __shfl_sync(0xffffffffu, nr, j);
            int   rr = __shfl_sync(0xffffffffu, rv, j);
            float2 a = *reinterpret_cast<const float2*>(node_feat + (size_t)ss * 64 + 2 * l);
            float2 b = *reinterpret_cast<const float2*>(edge_feat + (size_t)ee * 64 + 2 * l);
            float mx = a.x * b.x * nn;
            float my = a.y * b.y * nn;
            if (rr) { r.x += mx; r.y += my; }
            else    { f.x += mx; f.y += my; }
        }
    }

    float* o = reinterpret_cast<float*>(g_S) + (size_t)n * 128;
    *reinterpret_cast<float2*>(o + 2 * l)      = f;
    *reinterpret_cast<float2*>(o + 64 + 2 * l) = r;
}

// ------------- split-bf16 mma.sync edge GEMM: out = edge_feat @ W -------------
// fp32 = hi(bf16, truncated) + lo(bf16 of residual); acc = hi*hi + hi*lo + lo*hi.
// R16 post-mortem: L1 96.7% was dominated by per-block B staging (4096 scalar
// 2B STS, ~8-way conflicts) + B ldmatrix — all grid-invariant. Now B fragments
// are precomputed ONCE (k_prep) and hot-loop B = coalesced L1-resident LDG.128.
// A tile doubled to 128 edges/block; smem is A-only.

#define MMA_BF16(c, a0, a1, a2, a3, b0, b1) \
    asm volatile( \
        "mma.sync.aligned.m16n8k16.row.col.f32.bf16.bf16.f32 " \
        "{%0,%1,%2,%3}, {%4,%5,%6,%7}, {%8,%9}, {%0,%1,%2,%3};" \
        : "+f"((c)[0]), "+f"((c)[1]), "+f"((c)[2]), "+f"((c)[3]) \
        : "r"(a0), "r"(a1), "r"(a2), "r"(a3), "r"(b0), "r"(b1))

#define LDSM4(r, addr) \
    asm volatile( \
        "ldmatrix.sync.aligned.m8n8.x4.shared.b16 {%0,%1,%2,%3}, [%4];" \
        : "=r"((r)[0]), "=r"((r)[1]), "=r"((r)[2]), "=r"((r)[3]) \
        : "r"(addr))

__device__ __forceinline__ void cvt_hilo_pair(float f0, float f1,
                                              u32& hi, u32& lo) {
    u32 u0 = __float_as_uint(f0), u1 = __float_as_uint(f1);
    hi = __byte_perm(u0, u1, 0x7632);             // {bf16_trunc(f1):bf16_trunc(f0)}
    float l0 = f0 - __uint_as_float(u0 & 0xFFFF0000u);
    float l1 = f1 - __uint_as_float(u1 & 0xFFFF0000u);
    asm("cvt.rn.bf16x2.f32 %0, %1, %2;" : "=r"(lo) : "f"(l1), "f"(l0));
}

// k_prep: one warp. Stage rel_w hi/lo into smem (144B pitch, [n][k]) exactly
// like R16's per-block staging, then run the identical ldmatrix address
// computation once per (ks, pair, hi/lo) and store the fragment registers.
__global__ __launch_bounds__(32) void k_prep(const float* __restrict__ rel_w) {
    __shared__ char sm[18432];      // BH 0..9216, BL 9216..18432
    const int lane = threadIdx.x;

    for (int idx = lane; idx < 4096; idx += 32) {
        int k = idx >> 6;
        int n = idx & 63;
        float f = rel_w[k * 64 + n];
        u32 u = __float_as_uint(f);
        int off = n * 144 + k * 2;
        *reinterpret_cast<uint16_t*>(sm + off) = (uint16_t)(u >> 16);
        float l = f - __uint_as_float(u & 0xFFFF0000u);
        *reinterpret_cast<__nv_bfloat16*>(sm + 9216 + off) = __float2bfloat16(l);
    }
    __syncwarp();

    u32 smb = (u32)__cvta_generic_to_shared(sm);
    int bn = lane & 7;
    int kh = (lane >> 3) & 1;
    int js = lane >> 4;
    #pragma unroll
    for (int ks = 0; ks < 4; ks++) {
        #pragma unroll
        for (int p = 0; p < 4; p++) {
            u32 boff = (u32)(((2 * p + js) * 8 + bn) * 144 + kh * 16 + ks * 32);
            u32 bh[4], bl[4];
            LDSM4(bh, smb + boff);
            LDSM4(bl, smb + 9216 + boff);
            int slot = (ks * 4 + p) * 2;
            g_Bfrag[slot][lane]     = make_uint4(bh[0], bh[1], bh[2], bh[3]);
            g_Bfrag[slot + 1][lane] = make_uint4(bl[0], bl[1], bl[2], bl[3]);
        }
    }
}

#define SH_AH 0
#define SH_AL 18432
// total 36864 bytes static shared (A only; 128 rows x 144B, hi+lo)

__global__ __launch_bounds__(128) void k_edge_mma(
    const float* __restrict__ edge_feat,
    float* __restrict__ edge_out)
{
    __shared__ char sm[36864];

    const int tid = threadIdx.x;
    const int e0  = blockIdx.x * 128;

    // --- A: edge_feat tile [128 rows x 64 k] -> hi/lo bf16 smem ---
    {
        const float4* Ag = reinterpret_cast<const float4*>(edge_feat) + (size_t)e0 * 16;
        #pragma unroll
        for (int it = 0; it < 16; it++) {
            int idx = it * 128 + tid;        // 0..2047
            int r  = idx >> 4;
            int q  = idx & 15;
            float4 v = Ag[(size_t)r * 16 + q];
            u32 h0, l0, h1, l1;
            cvt_hilo_pair(v.x, v.y, h0, l0);
            cvt_hilo_pair(v.z, v.w, h1, l1);
            int byte = r * 144 + q * 8;
            *reinterpret_cast<uint2*>(sm + SH_AH + byte) = make_uint2(h0, h1);
            *reinterpret_cast<uint2*>(sm + SH_AL + byte) = make_uint2(l0, l1);
        }
    }
    __syncthreads();

    // --- mma mainloop: warp w owns rows [32w, 32w+32) = 2 m16 tiles ---
    const int w    = tid >> 5;
    const int lane = tid & 31;
    const int gid  = lane >> 2;
    const int t2   = (lane & 3) * 2;

    u32 smb = (u32)__cvta_generic_to_shared(sm);

    // A ldmatrix lane addresses for tiles T=0,1
    u32 a_addr[2];
    #pragma unroll
    for (int T = 0; T < 2; T++) {
        int arow = w * 32 + T * 16 + ((lane >> 3) & 1) * 8 + (lane & 7);
        a_addr[T] = smb + (u32)(arow * 144 + (lane >> 4) * 16);
    }

    float c[2][8][4];
    #pragma unroll
    for (int T = 0; T < 2; T++)
        #pragma unroll
        for (int j = 0; j < 8; j++)
            #pragma unroll
            for (int q = 0; q < 4; q++) c[T][j][q] = 0.f;

    #pragma unroll
    for (int ks = 0; ks < 4; ks++) {
        u32 ko = ks * 32;
        u32 ah[2][4], al[2][4];
        #pragma unroll
        for (int T = 0; T < 2; T++) {
            LDSM4(ah[T], a_addr[T] + ko);
            LDSM4(al[T], a_addr[T] + SH_AL + ko);
        }
        #pragma unroll
        for (int p = 0; p < 4; p++) {
            int slot = (ks * 4 + p) * 2;
            uint4 bh = __ldg(&g_Bfrag[slot][lane]);
            uint4 bl = __ldg(&g_Bfrag[slot + 1][lane]);
            #pragma unroll
            for (int T = 0; T < 2; T++) {
                MMA_BF16(c[T][2 * p],     ah[T][0], ah[T][1], ah[T][2], ah[T][3], bh.x, bh.y);
                MMA_BF16(c[T][2 * p],     ah[T][0], ah[T][1], ah[T][2], ah[T][3], bl.x, bl.y);
                MMA_BF16(c[T][2 * p],     al[T][0], al[T][1], al[T][2], al[T][3], bh.x, bh.y);
                MMA_BF16(c[T][2 * p + 1], ah[T][0], ah[T][1], ah[T][2], ah[T][3], bh.z, bh.w);
                MMA_BF16(c[T][2 * p + 1], ah[T][0], ah[T][1], ah[T][2], ah[T][3], bl.z, bl.w);
                MMA_BF16(c[T][2 * p + 1], al[T][0], al[T][1], al[T][2], al[T][3], bh.z, bh.w);
            }
        }
    }

    // --- epilogue ---
    #pragma unroll
    for (int T = 0; T < 2; T++) {
        int ra = w * 32 + T * 16 + gid;
        float* oa = edge_out + (size_t)(e0 + ra) * 64;
        float* ob = edge_out + (size_t)(e0 + ra + 8) * 64;
        #pragma unroll
        for (int j = 0; j < 8; j++) {
            *reinterpret_cast<float2*>(oa + j * 8 + t2) = make_float2(c[T][j][0], c[T][j][1]);
            *reinterpret_cast<float2*>(ob + j * 8 + t2) = make_float2(c[T][j][2], c[T][j][3]);
        }
    }
}

// ----------------------------- node GEMM kernel ------------------------------
__global__ __launch_bounds__(64) void k_node(
    const float* __restrict__ node_feat,
    const float* __restrict__ in_w,
    const float* __restrict__ out_w,
    const float* __restrict__ loop_w,
    const float* __restrict__ loop_rel,
    const float* __restrict__ bias,
    float* __restrict__ node_out)
{
    __shared__ float Xs[64][68];
    __shared__ float Wt[64][68];

    const int t  = threadIdx.x;
    const int r0 = blockIdx.x * 64;
    const int tx = t & 7;
    const int ty = t >> 3;
    const float* S = reinterpret_cast<const float*>(g_S);

    u64 acc[8][8];
    #pragma unroll
    for (int i = 0; i < 8; i++)
        #pragma unroll
        for (int j = 0; j < 8; j++) acc[i][j] = 0ull;

    #pragma unroll 1
    for (int ch = 0; ch < 3; ch++) {
        if (ch == 2) {
            #pragma unroll 8
            for (int k = 0; k < 64; k++)
                Wt[t][k] = loop_w[k * 64 + t] * loop_rel[k];
        } else {
            const float* W = (ch == 0) ? in_w : out_w;
            #pragma unroll 8
            for (int k = 0; k < 64; k++)
                Wt[t][k] = W[k * 64 + t];
        }

        const float* Xbase;
        size_t pitch, off;
        if (ch == 0)      { Xbase = S;         pitch = 128; off = 0;  }
        else if (ch == 1) { Xbase = S;         pitch = 128; off = 64; }
        else              { Xbase = node_feat; pitch = 64;  off = 0;  }

        #pragma unroll
        for (int it = 0; it < 16; it++) {
            int idx = it * 64 + t;
            int rr = idx >> 4;
            int kq = idx & 15;
            int gr = r0 + rr;
            float4 v = make_float4(0.f, 0.f, 0.f, 0.f);
            if (gr < N_NODES)
                v = *reinterpret_cast<const float4*>(Xbase + (size_t)gr * pitch + off + kq * 4);
            *reinterpret_cast<float4*>(&Xs[rr][kq * 4]) = v;
        }
        __syncthreads();

        #pragma unroll 4
        for (int k4 = 0; k4 < 16; k4++) {
            ulonglong2 xv[8], wv[8];
            #pragma unroll
            for (int i = 0; i < 8; i++)
                xv[i] = *reinterpret_cast<const ulonglong2*>(&Xs[ty + 8 * i][k4 * 4]);
            #pragma unroll
            for (int j = 0; j < 8; j++)
                wv[j] = *reinterpret_cast<const ulonglong2*>(&Wt[tx + 8 * j][k4 * 4]);
            #pragma unroll
            for (int i = 0; i < 8; i++)
                #pragma unroll
                for (int j = 0; j < 8; j++)
                    FMA2(acc[i][j], xv[i].x, wv[j].x);
            #pragma unroll
            for (int i = 0; i < 8; i++)
                #pragma unroll
                for (int j = 0; j < 8; j++)
                    FMA2(acc[i][j], xv[i].y, wv[j].y);
        }
        __syncthreads();
    }

    #pragma unroll
    for (int i = 0; i < 8; i++) {
        int rr = r0 + ty + 8 * i;
        if (rr < N_NODES) {
            float* o = node_out + (size_t)rr * 64;
            #pragma unroll
            for (int j = 0; j < 8; j++) {
                int c = tx + 8 * j;
                F2U cv; cv.u = acc[i][j];
                o[c] = (cv.f.x + cv.f.y) * 0.3333333f + __ldg(&bias[c]);
            }
        }
    }
}

// ---------------------------------------------------------------------------
// kernel_launch — inputs in setup_inputs dict order; is_rev is int32.
// Output: node_out [N,64] then edge_out [E,64], f32. Single stream.
// k_edge_mma stays at sampled launch index 3 for ncu.
// ---------------------------------------------------------------------------
extern "C" void kernel_launch(void* const* d_in, const int* in_sizes, int n_in,
                              void* d_out, int out_size)
{
    const float* node_feat = (const float*)d_in[0];
    const float* edge_feat = (const float*)d_in[1];
    const float* edge_norm = (const float*)d_in[2];
    const int*   src       = (const int*)d_in[3];
    const int*   dst       = (const int*)d_in[4];
    const int*   is_rev    = (const int*)d_in[5];
    const float* in_w      = (const float*)d_in[6];
    const float* out_w     = (const float*)d_in[7];
    const float* rel_w     = (const float*)d_in[8];
    const float* loop_w    = (const float*)d_in[9];
    const float* loop_rel  = (const float*)d_in[10];
    const float* bias      = (const float*)d_in[11];

    float* out      = (float*)d_out;
    float* node_out = out;

    int write_edge = (out_size >= (N_NODES + N_EDGES) * D) ? 1 : 0;
    float* edge_out = write_edge ? (out + (size_t)N_NODES * D) : nullptr;

    k_prep<<<1, 32>>>(rel_w);                                    // 0
    k_hist<<<(N_EDGES + 255) / 256, 256>>>(dst);                 // 1
    k_scanA<<<N_SCAN_BLKS, SCAN_BLK>>>();                        // 2
    if (write_edge)
        k_edge_mma<<<N_EDGES / 128, 128>>>(edge_feat, edge_out); // 3
    k_scanB<<<1, 512>>>();                                       // 4
    k_scanC<<<N_SCAN_BLKS, SCAN_BLK>>>();                        // 5
    k_perm<<<(N_EDGES + 255) / 256, 256>>>(dst);                 // 6
    k_agg<<<(N_NODES * 32 + 255) / 256, 256>>>(node_feat, edge_feat,
                                               edge_norm, src, is_rev); // 7
    k_node<<<(N_NODES + 63) / 64, 64>>>(node_feat, in_w, out_w,
                                        loop_w, loop_rel, bias, node_out); // 8
}